// round 13
// baseline (speedup 1.0000x reference)
#include <cuda_runtime.h>
#include <math.h>

// Problem constants (fixed by the reference setup)
#define Bc 8
#define Mc 384
#define Nc 1536
#define Lc 20
#define RWc 8
#define Ec (Mc * RWc)     // 3072 edges
#define TM 768            // threads per CTA
#define E4 (Ec / 4)       // 768 float4 groups per layer
#define EV2CAP 6144       // float2 slot capacity (worst case 4608)
#define GR 120            // grid size: all CTAs co-resident (1/SM, <=148)
#define GT (GR * TM)      // 92160 grid threads

// Dynamic shared layout:
//   ev  : EV2CAP float2 (interleaved {S-contrib, belief-contrib} slots)
//   sS  : Nc floats     (per-column variable-node sums)
//   col : Nc ints       (cnt during prologue -> colstart after scan)
#define SMEM_BYTES (EV2CAP * 8 + Nc * 4 + Nc * 4)

// Static device scratch (no allocation)
__device__ int    g_row_cnt[Mc];          // zero-init; re-zeroed in phase B
__device__ int4   g_ecol4[E4];            // edge -> column, 4 per thread
__device__ float4 g_cwde4[Lc * E4];       // compact per-edge wde, edge order
__device__ float4 g_cbse4[Lc * E4];       // compact llrs[c]*wllr[l][c]
__device__ float4 g_cmarg4[E4];           // compact marg_de per edge
__device__ float  g_bel[Bc * Lc * Nc];    // per-layer beliefs (for loss phase)

// Grid barrier state (sense-reversing, parity-indexed counters)
__device__ int g_gen;
__device__ int g_cnt[2];

__device__ __forceinline__ void gridbar() {
    __syncthreads();
    if (threadIdx.x == 0) {
        __threadfence();                       // publish this CTA's writes
        int gen = *(volatile int*)&g_gen;
        int idx = gen & 1;
        if (atomicAdd(&g_cnt[idx], 1) == GR - 1) {
            g_cnt[idx] = 0;
            __threadfence();
            atomicAdd(&g_gen, 1);
        } else {
            while (*(volatile int*)&g_gen == gen) __nanosleep(64);
        }
    }
    __syncthreads();
}

__device__ __forceinline__ float tanh_fast(float x) {
    float y;
    asm("tanh.approx.f32 %0, %1;" : "=f"(y) : "f"(x));
    return y;
}

// ---------------------------------------------------------------------------
// Single fused kernel: extract -> gather -> BP main (CTAs 0..7) -> loss.
// ---------------------------------------------------------------------------
__global__ void __launch_bounds__(TM, 1) k_all(
    const float* __restrict__ H,
    const float* __restrict__ synd,      // (B, M, 1)
    const float* __restrict__ errors,    // (B, N)
    const float* __restrict__ llrs,      // (N)
    const float* __restrict__ wde,       // (L, M, N)
    const float* __restrict__ wllr,      // (L, N)
    const float* __restrict__ marg_de,   // (M, N)
    const float* __restrict__ marg_llr,  // (N)
    const float* __restrict__ resw,      // (L)
    const float* __restrict__ rhos,      // (L)
    float* __restrict__ out)
{
    extern __shared__ unsigned char smem[];
    float2* ev  = (float2*)smem;             // EV2CAP
    float*  sS  = (float*)(ev + EV2CAP);     // Nc
    int*    col = (int*)(sS + Nc);           // Nc: cnt -> colstart

    __shared__ int   s_wsum[TM / 32], s_wscan[32];
    __shared__ float s_rw[Lc];
    __shared__ float s_red[TM / 32];

    const int bid = blockIdx.x;
    const int t   = threadIdx.x;
    const int gtid = bid * TM + t;
    const int lane = t & 31, wid = t >> 5;

    // ================= Phase A: extract H sparsity =================
    // One float4 per item (rows are 384 float4s wide -> never cross rows).
    for (int idx = gtid; idx < Mc * Nc / 4; idx += GT) {
        const float4 h = ((const float4*)H)[idx];
        if (h.x != 0.f || h.y != 0.f || h.z != 0.f || h.w != 0.f) {
            const int m  = idx / (Nc / 4);
            const int c0 = (idx - m * (Nc / 4)) * 4;
            int* ecol = (int*)g_ecol4;
            if (h.x != 0.f) ecol[m * RWc + atomicAdd(&g_row_cnt[m], 1)] = c0 + 0;
            if (h.y != 0.f) ecol[m * RWc + atomicAdd(&g_row_cnt[m], 1)] = c0 + 1;
            if (h.z != 0.f) ecol[m * RWc + atomicAdd(&g_row_cnt[m], 1)] = c0 + 2;
            if (h.w != 0.f) ecol[m * RWc + atomicAdd(&g_row_cnt[m], 1)] = c0 + 3;
        }
    }
    if (gtid == 0) out[0] = 0.f;
    gridbar();

    // ================= Phase B: gather/compact weights =================
    if (gtid < Lc * Ec) {
        const int i = gtid;
        const int l = i / Ec;
        const int e = i - l * Ec;
        const int c = ((const int*)g_ecol4)[e];
        const int m = e >> 3;
        ((float*)g_cwde4)[i] = wde[(l * Mc + m) * Nc + c];
        ((float*)g_cbse4)[i] = llrs[c] * wllr[l * Nc + c];
        if (l == 0) {
            ((float*)g_cmarg4)[e] = marg_de[m * Nc + c];
            if (e < Mc) g_row_cnt[e] = 0;   // reset for next replay
        }
    }
    gridbar();

    // ================= Phase C: BP main (CTAs 0..7) =================
    if (bid < Bc) {
        const int b = bid;
        const int r = t >> 1;
        const int ca = 2 * t, cb = 2 * t + 1;

        // ---- prologue: zero slots, count column degrees ----
        for (int i = t; i < EV2CAP; i += TM) ev[i] = make_float2(0.f, 0.f);
        col[ca] = 0; col[cb] = 0;
        if (t < Lc) s_rw[t] = resw[t];
        __syncthreads();

        const int4 c4 = g_ecol4[t];
        int rk0 = atomicAdd(&col[c4.x], 1);
        int rk1 = atomicAdd(&col[c4.y], 1);
        int rk2 = atomicAdd(&col[c4.z], 1);
        int rk3 = atomicAdd(&col[c4.w], 1);
        __syncthreads();

        // 2-padded degrees + block exclusive scan -> column segment starts
        const int dega = col[ca], degb = col[cb];
        const int pad_a = (dega + 1) & ~1, pad_b = (degb + 1) & ~1;
        const int tsum = pad_a + pad_b;
        int x = tsum;
#pragma unroll
        for (int o = 1; o < 32; o <<= 1) {
            int y = __shfl_up_sync(0xffffffffu, x, o);
            if (lane >= o) x += y;
        }
        if (lane == 31) s_wsum[wid] = x;
        __syncthreads();
        if (t < 32) {
            int vv = (t < TM / 32) ? s_wsum[t] : 0;
#pragma unroll
            for (int o = 1; o < 32; o <<= 1) {
                int y = __shfl_up_sync(0xffffffffu, vv, o);
                if (t >= o) vv += y;
            }
            s_wscan[t] = vv;
        }
        __syncthreads();
        const int tbase  = (wid ? s_wscan[wid - 1] : 0) + (x - tsum);
        const int starta = tbase, startb = tbase + pad_a;
        col[ca] = starta; col[cb] = startb;   // overwrite cnt with colstart
        __syncthreads();

        const int sl0 = col[c4.x] + rk0;
        const int sl1 = col[c4.y] + rk1;
        const int sl2 = col[c4.z] + rk2;
        const int sl3 = col[c4.w] + rk3;
        const int pass_a = pad_a >> 1, pass_b = pad_b >> 1;  // float4 reads
        const int s4a = starta >> 1, s4b = startb >> 1;

        // ---- per-thread constants ----
        const float4 mg4 = g_cmarg4[t];
        const float  sgn = 1.f - 2.f * synd[b * Mc + r];
        const float  lma = llrs[ca] * marg_llr[ca];
        const float  lmb = llrs[cb] * marg_llr[cb];
        float* belrow = g_bel + (b * Lc) * Nc;

        ((float2*)sS)[t] = make_float2(0.f, 0.f);  // layer-0 sums (msg = 0)
        float msg0 = 0.f, msg1 = 0.f, msg2 = 0.f, msg3 = 0.f;
        float4 bs = g_cbse4[t];
        __syncthreads();

        for (int l = 0; l < Lc; l++) {
            // prefetch next layer's weights first; MUFU chain hides L2
            float4 nwd, nbs;
            if (l < Lc - 1) {
                nwd = g_cwde4[(l + 1) * E4 + t];
                nbs = g_cbse4[(l + 1) * E4 + t];
            } else {
                nwd = make_float4(0.f, 0.f, 0.f, 0.f);
                nbs = bs;
            }

            // ---- C: check-node update ----
            float me0 = bs.x + sS[c4.x] - msg0;
            float me1 = bs.y + sS[c4.y] - msg1;
            float me2 = bs.z + sS[c4.z] - msg2;
            float me3 = bs.w + sS[c4.w] - msg3;
            float d0 = tanh_fast(0.5f * me0); if (d0 == 0.f) d0 = 1.f;
            float d1 = tanh_fast(0.5f * me1); if (d1 == 0.f) d1 = 1.f;
            float d2 = tanh_fast(0.5f * me2); if (d2 == 0.f) d2 = 1.f;
            float d3 = tanh_fast(0.5f * me3); if (d3 == 0.f) d3 = 1.f;
            float lp = d0 * d1 * d2 * d3;
            float p  = lp * __shfl_xor_sync(0xffffffffu, lp, 1);

            const float rw = s_rw[l];
            float nm0 = __logf(__fdividef(d0 + p, d0 - p)) * sgn + rw * msg0;
            float nm1 = __logf(__fdividef(d1 + p, d1 - p)) * sgn + rw * msg1;
            float nm2 = __logf(__fdividef(d2 + p, d2 - p)) * sgn + rw * msg2;
            float nm3 = __logf(__fdividef(d3 + p, d3 - p)) * sgn + rw * msg3;
            msg0 = nm0; msg1 = nm1; msg2 = nm2; msg3 = nm3;

            // scatter interleaved {S-contrib, belief-contrib} slots
            ev[sl0] = make_float2(nm0 * nwd.x, nm0 * mg4.x);
            ev[sl1] = make_float2(nm1 * nwd.y, nm1 * mg4.y);
            ev[sl2] = make_float2(nm2 * nwd.z, nm2 * mg4.z);
            ev[sl3] = make_float2(nm3 * nwd.w, nm3 * mg4.w);
            bs = nbs;
            __syncthreads();

            // ---- BD: contiguous float4 gather -> S + beliefs ----
            float Sa = 0.f, Ba = 0.f;
            for (int j = 0; j < pass_a; j++) {
                float4 v = ((const float4*)ev)[s4a + j];
                Sa += v.x + v.z;  Ba += v.y + v.w;
            }
            float Sb = 0.f, Bb = 0.f;
            for (int j = 0; j < pass_b; j++) {
                float4 v = ((const float4*)ev)[s4b + j];
                Sb += v.x + v.z;  Bb += v.y + v.w;
            }
            ((float2*)sS)[t] = make_float2(Sa, Sb);
            ((float2*)(belrow + l * Nc))[t] = make_float2(Ba + lma, Bb + lmb);
            __syncthreads();
        }
    }
    gridbar();   // fence inside publishes g_bel

    // ================= Phase D: loss (full grid) =================
    float v = 0.f;
    for (int i = gtid; i < Bc * Lc * Nc; i += GT) {
        const int c = i % Nc;
        const int l = (i / Nc) % Lc;
        const int b = i / (Lc * Nc);
        float bel = g_bel[i];
        float sp  = fmaxf(bel, 0.f) + __logf(1.f + __expf(-fabsf(bel)));
        v += rhos[l] * (sp - (1.f - errors[b * Nc + c]) * bel);
    }
#pragma unroll
    for (int o = 16; o; o >>= 1) v += __shfl_down_sync(0xffffffffu, v, o);
    if (lane == 0) s_red[wid] = v;
    __syncthreads();
    if (t < 32) {
        float s = (t < TM / 32) ? s_red[t] : 0.f;
#pragma unroll
        for (int o = 16; o; o >>= 1) s += __shfl_down_sync(0xffffffffu, s, o);
        if (t == 0 && s != 0.f) atomicAdd(out, s * (1.f / (float)Bc));
        if (t == 0 && s == 0.f) atomicAdd(out, 0.f);   // keep deterministic path
    }
}

// ---------------------------------------------------------------------------
extern "C" void kernel_launch(void* const* d_in, const int* in_sizes, int n_in,
                              void* d_out, int out_size) {
    const float* synd  = (const float*)d_in[0];
    const float* errs  = (const float*)d_in[1];
    const float* H     = (const float*)d_in[2];
    const float* llrs  = (const float*)d_in[3];
    const float* wde   = (const float*)d_in[4];
    const float* wllr  = (const float*)d_in[5];
    const float* mde   = (const float*)d_in[6];
    const float* mllr  = (const float*)d_in[7];
    const float* resw  = (const float*)d_in[8];
    const float* rhos  = (const float*)d_in[9];
    float* out = (float*)d_out;

    cudaFuncSetAttribute(k_all, cudaFuncAttributeMaxDynamicSharedMemorySize,
                         SMEM_BYTES);

    k_all<<<GR, TM, SMEM_BYTES>>>(H, synd, errs, llrs, wde, wllr,
                                  mde, mllr, resw, rhos, out);
}

// round 15
// speedup vs baseline: 1.0584x; 1.0584x over previous
#include <cuda_runtime.h>
#include <math.h>

// Problem constants (fixed by the reference setup)
#define Bc 8
#define Mc 384
#define Nc 1536
#define Lc 20
#define RWc 8
#define Ec (Mc * RWc)     // 3072 edges
#define TM 768            // k_main threads: 2 per row, 4 edges per thread
#define E4 (Ec / 4)       // 768 float4 groups per layer
#define EV2CAP 6144       // float2 slot capacity (worst case 4608)

// Dynamic shared layout:
//   ev  : EV2CAP float2 (interleaved {S-contrib, belief-contrib} slots,
//                        column-sorted, 2-slot padded)
//   sS  : Nc floats     (per-column variable-node sums)
//   col : Nc ints       (cnt during prologue -> colstart after scan)
#define SMEM_BYTES (EV2CAP * 8 + Nc * 4 + Nc * 4)

// Static device scratch (no allocation)
__device__ int    g_row_cnt[Mc];          // zero-init; re-zeroed by k_gather
__device__ int4   g_ecol4[E4];            // edge -> column, 4 per thread
__device__ float4 g_cwde4[Lc * E4];       // compact per-edge wde, edge order
__device__ float4 g_cbse4[Lc * E4];       // compact llrs[c]*wllr[l][c]
__device__ float4 g_cmarg4[E4];           // compact marg_de per edge

__device__ __forceinline__ float tanh_fast(float x) {
    float y;
    asm("tanh.approx.f32 %0, %1;" : "=f"(y) : "f"(x));
    return y;
}

// ---------------------------------------------------------------------------
// k_extract: full-chip H scan, one float4 per thread (rows = 384 float4s, so
// a float4 never crosses rows). Nonzeros claim slots via per-row atomics;
// slot order within a row is irrelevant (products/scatters commute).
// Counters are zero on entry (static init first call, k_gather re-zeroes).
// ---------------------------------------------------------------------------
__global__ void __launch_bounds__(1024) k_extract(
    const float* __restrict__ H, float* __restrict__ out)
{
    const int idx = blockIdx.x * 1024 + threadIdx.x;  // Mc*Nc/4 = 147456
    const float4 h = ((const float4*)H)[idx];
    if (h.x != 0.f || h.y != 0.f || h.z != 0.f || h.w != 0.f) {
        const int m  = idx / (Nc / 4);
        const int c0 = (idx - m * (Nc / 4)) * 4;
        int* ecol = (int*)g_ecol4;
        if (h.x != 0.f) ecol[m * RWc + atomicAdd(&g_row_cnt[m], 1)] = c0 + 0;
        if (h.y != 0.f) ecol[m * RWc + atomicAdd(&g_row_cnt[m], 1)] = c0 + 1;
        if (h.z != 0.f) ecol[m * RWc + atomicAdd(&g_row_cnt[m], 1)] = c0 + 2;
        if (h.w != 0.f) ecol[m * RWc + atomicAdd(&g_row_cnt[m], 1)] = c0 + 3;
    }
    if (idx == 0) out[0] = 0.f;
}

// ---------------------------------------------------------------------------
// k_gather: one thread per (layer, edge) — 61440 threads, full-chip MLP.
// Compacts wde / llrs*wllr / marg_de into edge order; resets row counters.
// ---------------------------------------------------------------------------
__global__ void __launch_bounds__(1024) k_gather(
    const float* __restrict__ llrs,
    const float* __restrict__ wde,
    const float* __restrict__ wllr,
    const float* __restrict__ marg_de)
{
    const int i = blockIdx.x * 1024 + threadIdx.x;  // Lc*Ec = 61440
    const int l = i / Ec;
    const int e = i - l * Ec;
    const int c = ((const int*)g_ecol4)[e];
    const int m = e >> 3;
    ((float*)g_cwde4)[i] = wde[(l * Mc + m) * Nc + c];
    ((float*)g_cbse4)[i] = llrs[c] * wllr[l * Nc + c];
    if (l == 0) {
        ((float*)g_cmarg4)[e] = marg_de[m * Nc + c];
        if (e < Mc) g_row_cnt[e] = 0;   // reset for next replay
    }
}

// ---------------------------------------------------------------------------
// k_main: one CTA per batch. Thread t owns edges 4t..4t+3 (half of row t>>1)
// on the row side, columns {2t, 2t+1} on the column side. Column data lives
// in interleaved float2 slots {S-contrib, belief-contrib}, column-sorted and
// 2-padded so BD reads float4s. Loss is folded into BD in registers (the
// belief is already register-resident there) — no gmem belief stream, no
// separate loss kernel. Per layer: 2 barriers, 0 atomics.
// ---------------------------------------------------------------------------
__global__ void __launch_bounds__(TM, 1) k_main(
    const float* __restrict__ synd,      // (B, M, 1)
    const float* __restrict__ errors,    // (B, N)
    const float* __restrict__ llrs,      // (N)
    const float* __restrict__ marg_llr,  // (N)
    const float* __restrict__ resw,      // (L)
    const float* __restrict__ rhos,      // (L)
    float* __restrict__ out)
{
    extern __shared__ unsigned char smem[];
    float2* ev  = (float2*)smem;             // EV2CAP
    float*  sS  = (float*)(ev + EV2CAP);     // Nc
    int*    col = (int*)(sS + Nc);           // Nc: cnt -> colstart

    __shared__ int   s_wsum[TM / 32], s_wscan[32];
    __shared__ float s_rw[Lc], s_rho[Lc], s_red[TM / 32];

    const int b = blockIdx.x;
    const int t = threadIdx.x;
    const int r = t >> 1;
    const int ca = 2 * t, cb = 2 * t + 1;
    const int lane = t & 31, wid = t >> 5;

    // ---- prologue: zero slots, count column degrees ----
    for (int i = t; i < EV2CAP; i += TM) ev[i] = make_float2(0.f, 0.f);
    col[ca] = 0; col[cb] = 0;
    if (t < Lc) { s_rw[t] = resw[t]; s_rho[t] = rhos[t]; }
    __syncthreads();

    const int4 c4 = g_ecol4[t];
    int rk0 = atomicAdd(&col[c4.x], 1);
    int rk1 = atomicAdd(&col[c4.y], 1);
    int rk2 = atomicAdd(&col[c4.z], 1);
    int rk3 = atomicAdd(&col[c4.w], 1);
    __syncthreads();

    // 2-padded degrees + block exclusive scan -> even column segment starts
    const int dega = col[ca], degb = col[cb];
    const int pad_a = (dega + 1) & ~1, pad_b = (degb + 1) & ~1;
    const int tsum = pad_a + pad_b;
    int x = tsum;
#pragma unroll
    for (int o = 1; o < 32; o <<= 1) {
        int y = __shfl_up_sync(0xffffffffu, x, o);
        if (lane >= o) x += y;
    }
    if (lane == 31) s_wsum[wid] = x;
    __syncthreads();
    if (t < 32) {
        int vv = (t < TM / 32) ? s_wsum[t] : 0;
#pragma unroll
        for (int o = 1; o < 32; o <<= 1) {
            int y = __shfl_up_sync(0xffffffffu, vv, o);
            if (t >= o) vv += y;
        }
        s_wscan[t] = vv;
    }
    __syncthreads();
    const int tbase  = (wid ? s_wscan[wid - 1] : 0) + (x - tsum);
    const int starta = tbase, startb = tbase + pad_a;
    col[ca] = starta; col[cb] = startb;   // overwrite cnt with colstart
    __syncthreads();

    const int sl0 = col[c4.x] + rk0;
    const int sl1 = col[c4.y] + rk1;
    const int sl2 = col[c4.z] + rk2;
    const int sl3 = col[c4.w] + rk3;
    const int pass_a = pad_a >> 1, pass_b = pad_b >> 1;  // float4 reads
    const int s4a = starta >> 1, s4b = startb >> 1;

    // ---- per-thread constants in registers ----
    const float4 mg4 = g_cmarg4[t];
    const float  sgn = 1.f - 2.f * synd[b * Mc + r];
    const float  lma = llrs[ca] * marg_llr[ca];
    const float  lmb = llrs[cb] * marg_llr[cb];
    const float  oma = 1.f - errors[b * Nc + ca];
    const float  omb = 1.f - errors[b * Nc + cb];

    ((float2*)sS)[t] = make_float2(0.f, 0.f);  // layer-0 sums (msg = 0)
    float msg0 = 0.f, msg1 = 0.f, msg2 = 0.f, msg3 = 0.f;
    float4 bs = g_cbse4[t];              // layer-0 base
    float loss = 0.f;
    __syncthreads();

    for (int l = 0; l < Lc; l++) {
        // Issue next-layer weight prefetch FIRST; MUFU chain below hides L2.
        float4 nwd, nbs;
        if (l < Lc - 1) {
            nwd = g_cwde4[(l + 1) * E4 + t];
            nbs = g_cbse4[(l + 1) * E4 + t];
        } else {
            nwd = make_float4(0.f, 0.f, 0.f, 0.f);
            nbs = bs;
        }

        // ---- C: check-node update for layer l ----
        float me0 = bs.x + sS[c4.x] - msg0;
        float me1 = bs.y + sS[c4.y] - msg1;
        float me2 = bs.z + sS[c4.z] - msg2;
        float me3 = bs.w + sS[c4.w] - msg3;
        float d0 = tanh_fast(0.5f * me0); if (d0 == 0.f) d0 = 1.f;
        float d1 = tanh_fast(0.5f * me1); if (d1 == 0.f) d1 = 1.f;
        float d2 = tanh_fast(0.5f * me2); if (d2 == 0.f) d2 = 1.f;
        float d3 = tanh_fast(0.5f * me3); if (d3 == 0.f) d3 = 1.f;
        float lp = d0 * d1 * d2 * d3;
        float p  = lp * __shfl_xor_sync(0xffffffffu, lp, 1);  // full row product

        const float rw = s_rw[l];
        float nm0 = __logf(__fdividef(d0 + p, d0 - p)) * sgn + rw * msg0;
        float nm1 = __logf(__fdividef(d1 + p, d1 - p)) * sgn + rw * msg1;
        float nm2 = __logf(__fdividef(d2 + p, d2 - p)) * sgn + rw * msg2;
        float nm3 = __logf(__fdividef(d3 + p, d3 - p)) * sgn + rw * msg3;
        msg0 = nm0; msg1 = nm1; msg2 = nm2; msg3 = nm3;

        // Scatter interleaved {S-contrib, belief-contrib} slots (STS.64 x4)
        ev[sl0] = make_float2(nm0 * nwd.x, nm0 * mg4.x);
        ev[sl1] = make_float2(nm1 * nwd.y, nm1 * mg4.y);
        ev[sl2] = make_float2(nm2 * nwd.z, nm2 * mg4.z);
        ev[sl3] = make_float2(nm3 * nwd.w, nm3 * mg4.w);
        bs = nbs;
        __syncthreads();

        // ---- BD: float4 gather -> S (next layer) + loss (this layer) ----
        const float rho = s_rho[l];
        float Sa = 0.f, Ba = 0.f;
        for (int j = 0; j < pass_a; j++) {
            float4 v = ((const float4*)ev)[s4a + j];
            Sa += v.x + v.z;  Ba += v.y + v.w;
        }
        float Sb = 0.f, Bb = 0.f;
        for (int j = 0; j < pass_b; j++) {
            float4 v = ((const float4*)ev)[s4b + j];
            Sb += v.x + v.z;  Bb += v.y + v.w;
        }
        ((float2*)sS)[t] = make_float2(Sa, Sb);

        float bela = Ba + lma;
        float belb = Bb + lmb;
        float spa  = fmaxf(bela, 0.f) + __logf(1.f + __expf(-fabsf(bela)));
        float spb  = fmaxf(belb, 0.f) + __logf(1.f + __expf(-fabsf(belb)));
        loss += rho * ((spa - oma * bela) + (spb - omb * belb));
        __syncthreads();
    }

    // ---- block reduction -> atomic accumulate mean over batch ----
#pragma unroll
    for (int o = 16; o; o >>= 1) loss += __shfl_down_sync(0xffffffffu, loss, o);
    if (lane == 0) s_red[wid] = loss;
    __syncthreads();
    if (t < 32) {
        float v = (t < TM / 32) ? s_red[t] : 0.f;
#pragma unroll
        for (int o = 16; o; o >>= 1) v += __shfl_down_sync(0xffffffffu, v, o);
        if (t == 0) atomicAdd(out, v * (1.f / (float)Bc));
    }
}

// ---------------------------------------------------------------------------
extern "C" void kernel_launch(void* const* d_in, const int* in_sizes, int n_in,
                              void* d_out, int out_size) {
    const float* synd  = (const float*)d_in[0];
    const float* errs  = (const float*)d_in[1];
    const float* H     = (const float*)d_in[2];
    const float* llrs  = (const float*)d_in[3];
    const float* wde   = (const float*)d_in[4];
    const float* wllr  = (const float*)d_in[5];
    const float* mde   = (const float*)d_in[6];
    const float* mllr  = (const float*)d_in[7];
    const float* resw  = (const float*)d_in[8];
    const float* rhos  = (const float*)d_in[9];
    float* out = (float*)d_out;

    cudaFuncSetAttribute(k_main, cudaFuncAttributeMaxDynamicSharedMemorySize,
                         SMEM_BYTES);

    k_extract<<<(Mc * Nc / 4) / 1024, 1024>>>(H, out);
    k_gather<<<(Lc * Ec) / 1024, 1024>>>(llrs, wde, wllr, mde);
    k_main<<<Bc, TM, SMEM_BYTES>>>(synd, errs, llrs, mllr, resw, rhos, out);
}